// round 6
// baseline (speedup 1.0000x reference)
#include <cuda_runtime.h>

#define NMAX 100000
#define EMAXN 1600000

// ---- scratch (device globals; no allocation allowed). 16B-aligned for float4 access ----
__device__ __align__(16) float g_xw[NMAX * 64];     // [N][64]: cols 0..31 = x@W_rel1, 32..63 = x@W_root1
__device__ __align__(16) float g_sum1[NMAX * 32];   // edge-aggregated projected messages (layer 1)
__device__ __align__(16) float g_cnt[NMAX];         // in-degree (float)
__device__ __align__(16) float g_hr[NMAX * 8];      // h@W_rel2 padded to 8 (cols 5..7 = 0)
__device__ __align__(16) float g_hroot[NMAX * 8];   // h@W_root2 padded to 8
__device__ __align__(16) float g_sum2[NMAX * 8];    // edge-aggregated layer-2 messages
__device__ __align__(16) int   g_src[EMAXN];
__device__ __align__(16) int   g_dst[EMAXN];
__device__ int g_is64;

// ---- K-1: detect whether edge_index buffer is int64 (all high words zero) or int32 ----
__global__ void k_detect(const int* __restrict__ ei) {
    if (threadIdx.x == 0 && blockIdx.x == 0) {
        int all_zero = 1;
        for (int i = 1; i < 128; i += 2)
            if (ei[i] != 0) { all_zero = 0; break; }
        g_is64 = all_zero;
    }
}

// ---- K-0b: unpack indices into clean int32 arrays (clamped for safety) ----
__global__ void __launch_bounds__(256) k_unpack(const int* __restrict__ ei, int E, int N) {
    int e = blockIdx.x * 256 + threadIdx.x;
    if (e >= E) return;
    int s, d;
    if (g_is64) {            // int64 layout: value at low word, dst row begins at word 2E
        s = ei[2 * e];
        d = ei[2 * E + 2 * e];
    } else {                 // int32 layout: [src[0..E), dst[0..E)]
        s = ei[e];
        d = ei[E + e];
    }
    if (s < 0 || s >= N) s = 0;
    if (d < 0 || d >= N) d = 0;
    g_src[e] = s;
    g_dst[e] = d;
}

// ---- K0: zero the accumulators ----
__global__ void k_zero(int N) {
    int i = blockIdx.x * blockDim.x + threadIdx.x;
    int stride = gridDim.x * blockDim.x;
    for (int j = i; j < N * 32; j += stride) g_sum1[j] = 0.f;
    for (int j = i; j < N * 8;  j += stride) g_sum2[j] = 0.f;
    for (int j = i; j < N;      j += stride) g_cnt[j]  = 0.f;
}

// ---- K1: fused projection  g_xw = x @ [W_rel1 | W_root1]  (128 -> 64) ----
__global__ void __launch_bounds__(256) k_gemm1(
    const float* __restrict__ x,
    const float* __restrict__ Wrel,
    const float* __restrict__ Wroot,
    int N)
{
    __shared__ float Ws[64 * 64];    // [kk][col]
    __shared__ float Xs[64 * 68];    // [kk][node], pitch 68
    const int t  = threadIdx.x;
    const int tx = t & 15;
    const int ty = t >> 4;
    const int n0 = blockIdx.x * 64;

    float acc[4][4] = {};

    for (int kc = 0; kc < 128; kc += 64) {
        #pragma unroll
        for (int i = t; i < 64 * 64; i += 256) {
            int kk = i >> 6, col = i & 63;
            float w = (col < 32) ? Wrel[(kc + kk) * 32 + col]
                                 : Wroot[(kc + kk) * 32 + (col - 32)];
            Ws[kk * 64 + col] = w;
        }
        #pragma unroll
        for (int i = t; i < 64 * 64; i += 256) {
            int k = i & 63, n = i >> 6;
            int node = n0 + n;
            Xs[k * 68 + n] = (node < N) ? x[node * 128 + kc + k] : 0.f;
        }
        __syncthreads();
        #pragma unroll 8
        for (int kk = 0; kk < 64; kk++) {
            float4 a = *(const float4*)&Xs[kk * 68 + ty * 4];
            float4 b = *(const float4*)&Ws[kk * 64 + tx * 4];
            acc[0][0] += a.x * b.x; acc[0][1] += a.x * b.y; acc[0][2] += a.x * b.z; acc[0][3] += a.x * b.w;
            acc[1][0] += a.y * b.x; acc[1][1] += a.y * b.y; acc[1][2] += a.y * b.z; acc[1][3] += a.y * b.w;
            acc[2][0] += a.z * b.x; acc[2][1] += a.z * b.y; acc[2][2] += a.z * b.z; acc[2][3] += a.z * b.w;
            acc[3][0] += a.w * b.x; acc[3][1] += a.w * b.y; acc[3][2] += a.w * b.z; acc[3][3] += a.w * b.w;
        }
        __syncthreads();
    }

    #pragma unroll
    for (int i = 0; i < 4; i++) {
        int node = n0 + ty * 4 + i;
        if (node < N) {
            *(float4*)&g_xw[node * 64 + tx * 4] =
                make_float4(acc[i][0], acc[i][1], acc[i][2], acc[i][3]);
        }
    }
}

// ---- K2: edge pass 1 (weighted).  8 threads per edge, float4 each. ----
__global__ void __launch_bounds__(256) k_edge1(const float* __restrict__ ew, int E) {
    int t = blockIdx.x * 256 + threadIdx.x;
    int e = t >> 3, p = t & 7;
    if (e >= E) return;
    int s = g_src[e];
    int d = g_dst[e];
    float w = ew[e];
    float4 v = *(const float4*)&g_xw[s * 64 + p * 4];   // rel-projected cols 0..31
    float* dp = &g_sum1[d * 32 + p * 4];
    atomicAdd(dp + 0, v.x * w);
    atomicAdd(dp + 1, v.y * w);
    atomicAdd(dp + 2, v.z * w);
    atomicAdd(dp + 3, v.w * w);
    if (p == 0) atomicAdd(&g_cnt[d], 1.0f);
}

// ---- K3: combine layer 1 + project layer 2 ----
__global__ void __launch_bounds__(256) k_comb1(
    const float* __restrict__ b1,
    const float* __restrict__ Wrel2,    // [32][5]
    const float* __restrict__ Wroot2,   // [32][5]
    int N)
{
    __shared__ float sW[352];  // [0..159]=Wrel2, [160..319]=Wroot2, [320..351]=b1
    int t = threadIdx.x;
    for (int i = t; i < 352; i += 256) {          // FIXED: grid-stride fill (352 > 256!)
        sW[i] = (i < 160) ? Wrel2[i]
              : (i < 320) ? Wroot2[i - 160]
                          : b1[i - 320];
    }
    __syncthreads();

    int node = blockIdx.x * 256 + t;
    if (node >= N) return;

    float inv = 1.0f / fmaxf(g_cnt[node], 1.0f);
    const float4* sp = (const float4*)&g_sum1[node * 32];
    const float4* rp = (const float4*)&g_xw[node * 64 + 32];

    float h[32];
    #pragma unroll
    for (int q = 0; q < 8; q++) {
        float4 s4 = sp[q];
        float4 r4 = rp[q];
        h[4 * q + 0] = fmaxf(s4.x * inv + r4.x + sW[320 + 4 * q + 0], 0.f);
        h[4 * q + 1] = fmaxf(s4.y * inv + r4.y + sW[320 + 4 * q + 1], 0.f);
        h[4 * q + 2] = fmaxf(s4.z * inv + r4.z + sW[320 + 4 * q + 2], 0.f);
        h[4 * q + 3] = fmaxf(s4.w * inv + r4.w + sW[320 + 4 * q + 3], 0.f);
    }

    float hr[5] = {0.f, 0.f, 0.f, 0.f, 0.f};
    float ho[5] = {0.f, 0.f, 0.f, 0.f, 0.f};
    #pragma unroll
    for (int j = 0; j < 32; j++) {
        float hv = h[j];
        #pragma unroll
        for (int c = 0; c < 5; c++) {
            hr[c] += hv * sW[j * 5 + c];
            ho[c] += hv * sW[160 + j * 5 + c];
        }
    }
    *(float4*)&g_hr[node * 8 + 0]    = make_float4(hr[0], hr[1], hr[2], hr[3]);
    *(float4*)&g_hr[node * 8 + 4]    = make_float4(hr[4], 0.f, 0.f, 0.f);
    *(float4*)&g_hroot[node * 8 + 0] = make_float4(ho[0], ho[1], ho[2], ho[3]);
    *(float4*)&g_hroot[node * 8 + 4] = make_float4(ho[4], 0.f, 0.f, 0.f);
}

// ---- K4: edge pass 2 (unweighted).  4 threads per edge (cols 0..5; 5 real + 1 pad). ----
__global__ void __launch_bounds__(256) k_edge2(int E) {
    int t = blockIdx.x * 256 + threadIdx.x;
    int e = t >> 2, p = t & 3;
    if (e >= E) return;
    int s = g_src[e];
    int d = g_dst[e];
    if (p < 3) {
        float2 v = *(const float2*)&g_hr[s * 8 + p * 2];
        float* dp = &g_sum2[d * 8 + p * 2];
        atomicAdd(dp + 0, v.x);
        atomicAdd(dp + 1, v.y);
    }
}

// ---- K5: combine layer 2 + log_softmax ----
__global__ void __launch_bounds__(256) k_final(
    const float* __restrict__ b2,
    float* __restrict__ out,
    int N)
{
    int node = blockIdx.x * 256 + threadIdx.x;
    if (node >= N) return;
    float inv = 1.0f / fmaxf(g_cnt[node], 1.0f);
    float v[5];
    #pragma unroll
    for (int c = 0; c < 5; c++)
        v[c] = g_sum2[node * 8 + c] * inv + g_hroot[node * 8 + c] + b2[c];

    float m = v[0];
    #pragma unroll
    for (int c = 1; c < 5; c++) m = fmaxf(m, v[c]);
    float sum = 0.f;
    #pragma unroll
    for (int c = 0; c < 5; c++) sum += expf(v[c] - m);
    float lse = m + logf(sum);
    #pragma unroll
    for (int c = 0; c < 5; c++) out[node * 5 + c] = v[c] - lse;
}

extern "C" void kernel_launch(void* const* d_in, const int* in_sizes, int n_in,
                              void* d_out, int out_size)
{
    const float* x      = (const float*)d_in[0];
    const int*   ei     = (const int*)d_in[1];     // raw words; layout detected on device
    const float* ew     = (const float*)d_in[2];
    const float* Wrel1  = (const float*)d_in[3];
    const float* Wroot1 = (const float*)d_in[4];
    const float* b1     = (const float*)d_in[5];
    const float* Wrel2  = (const float*)d_in[6];
    const float* Wroot2 = (const float*)d_in[7];
    const float* b2     = (const float*)d_in[8];
    float*       out    = (float*)d_out;

    int N = out_size / 5;          // output [N,5]
    int E = in_sizes[1] / 2;       // edge_index [2,E]

    k_detect<<<1, 32>>>(ei);
    k_unpack<<<(E + 255) / 256, 256>>>(ei, E, N);
    k_zero  <<<2048, 256>>>(N);
    k_gemm1 <<<(N + 63) / 64, 256>>>(x, Wrel1, Wroot1, N);
    k_edge1 <<<(E * 8 + 255) / 256, 256>>>(ew, E);
    k_comb1 <<<(N + 255) / 256, 256>>>(b1, Wrel2, Wroot2, N);
    k_edge2 <<<(E * 4 + 255) / 256, 256>>>(E);
    k_final <<<(N + 255) / 256, 256>>>(b2, out, N);
}

// round 7
// speedup vs baseline: 1.3220x; 1.3220x over previous
#include <cuda_runtime.h>

#define NMAX 100000
#define EMAXN 1600000

// ---- scratch (device globals; no allocation allowed). 16B-aligned for float4/RED.128 ----
__device__ __align__(16) float g_xw[NMAX * 64];     // [N][64]: cols 0..31 = x@W_rel1, 32..63 = x@W_root1
__device__ __align__(16) float g_sum1[NMAX * 32];   // edge-aggregated projected messages (layer 1)
__device__ __align__(16) float g_cnt[NMAX];         // in-degree (float)
__device__ __align__(16) float g_hr[NMAX * 8];      // h@W_rel2 padded to 8 (cols 5..7 = 0)
__device__ __align__(16) float g_hroot[NMAX * 8];   // h@W_root2 padded to 8
__device__ __align__(16) float g_sum2[NMAX * 8];    // edge-aggregated layer-2 messages
__device__ __align__(16) int   g_src[EMAXN];
__device__ __align__(16) int   g_dst[EMAXN];
__device__ int g_is64;

// ---- helpers ----
__device__ __forceinline__ void ffma2(unsigned long long& d, unsigned long long a, unsigned long long b) {
    asm("fma.rn.f32x2 %0, %1, %2, %0;" : "+l"(d) : "l"(a), "l"(b));
}
__device__ __forceinline__ unsigned long long dup2(float a) {
    unsigned long long r;
    asm("mov.b64 %0, {%1, %1};" : "=l"(r) : "f"(a));
    return r;
}
__device__ __forceinline__ float2 u2f2(unsigned long long u) {
    float2 f;
    asm("mov.b64 {%0, %1}, %2;" : "=f"(f.x), "=f"(f.y) : "l"(u));
    return f;
}
__device__ __forceinline__ void red_add4(float* p, float4 v) {
    asm volatile("red.global.add.v4.f32 [%0], {%1,%2,%3,%4};"
                 :: "l"(p), "f"(v.x), "f"(v.y), "f"(v.z), "f"(v.w) : "memory");
}

// ---- K_detect: int64 vs int32 edge_index layout (parallel, warp-ballot) ----
__global__ void k_detect(const int* __restrict__ ei) {
    int lane = threadIdx.x;          // 64 threads
    int nz = 0;
    for (int i = lane * 2 + 1; i < 256; i += 128) nz |= ei[i];
    unsigned m = __ballot_sync(0xffffffff, nz != 0);
    m |= __shfl_xor_sync(0xffffffff, m, 0);   // no-op, keep lanes converged
    // combine across the 2 warps via shared
    __shared__ unsigned s[2];
    s[lane >> 5] = m;
    __syncthreads();
    if (lane == 0) g_is64 = ((s[0] | s[1]) == 0);
}

// ---- K0: zero the accumulators (runs before unpack, which accumulates cnt) ----
__global__ void k_zero(int N) {
    int i = blockIdx.x * blockDim.x + threadIdx.x;
    int stride = gridDim.x * blockDim.x;
    for (int j = i; j < N * 32; j += stride) g_sum1[j] = 0.f;
    for (int j = i; j < N * 8;  j += stride) g_sum2[j] = 0.f;
    for (int j = i; j < N;      j += stride) g_cnt[j]  = 0.f;
}

// ---- K_unpack: clean int32 indices + degree count ----
__global__ void __launch_bounds__(256) k_unpack(const int* __restrict__ ei, int E, int N) {
    int e = blockIdx.x * 256 + threadIdx.x;
    if (e >= E) return;
    int s, d;
    if (g_is64) { s = ei[2 * e];  d = ei[2 * E + 2 * e]; }
    else        { s = ei[e];      d = ei[E + e]; }
    if (s < 0 || s >= N) s = 0;
    if (d < 0 || d >= N) d = 0;
    g_src[e] = s;
    g_dst[e] = d;
    atomicAdd(&g_cnt[d], 1.0f);
}

// ---- K1: fused projection  g_xw = x @ [W_rel1 | W_root1]  (128 -> 64), f32x2 pipe ----
// 256-node x 64-col block tile, 256 threads, each 8 nodes x 8 cols (4 f32x2 pairs).
__global__ void __launch_bounds__(256) k_gemm1(
    const float* __restrict__ x,
    const float* __restrict__ Wrel,
    const float* __restrict__ Wroot,
    int N)
{
    extern __shared__ float sm[];
    float* Ws = sm;            // [64 k][64 c]   (4096 floats)
    float* Xs = sm + 4096;     // [256 node][69] (pitch 69 -> bank-spread scalar reads)

    const int t  = threadIdx.x;
    const int tx = t & 7;      // col group: cols tx*8 .. tx*8+7
    const int ty = t >> 3;     // node group: nodes ty*8 .. ty*8+7
    const int n0 = blockIdx.x * 256;

    unsigned long long acc[8][4];
    #pragma unroll
    for (int i = 0; i < 8; i++)
        #pragma unroll
        for (int j = 0; j < 4; j++) acc[i][j] = 0ull;

    for (int kc = 0; kc < 128; kc += 64) {
        // stage W chunk [64][64]
        #pragma unroll
        for (int i = t; i < 4096; i += 256) {
            int kk = i >> 6, col = i & 63;
            Ws[i] = (col < 32) ? Wrel[(kc + kk) * 32 + col]
                               : Wroot[(kc + kk) * 32 + (col - 32)];
        }
        // stage X chunk [256 nodes][64 k], row-major, coalesced float4 reads
        #pragma unroll
        for (int j = 0; j < 16; j++) {
            int idx  = t + 256 * j;          // 0..4095 float4 slots
            int kq   = idx & 15;
            int node = idx >> 4;
            int gn   = n0 + node;
            float4 v = (gn < N) ? *(const float4*)&x[gn * 128 + kc + kq * 4]
                                : make_float4(0.f, 0.f, 0.f, 0.f);
            float* dst = &Xs[node * 69 + kq * 4];
            dst[0] = v.x; dst[1] = v.y; dst[2] = v.z; dst[3] = v.w;
        }
        __syncthreads();

        const float* xrow = &Xs[(ty * 8) * 69];
        #pragma unroll 4
        for (int kk = 0; kk < 64; kk++) {
            ulonglong2 b01 = *(const ulonglong2*)&Ws[kk * 64 + tx * 8];
            ulonglong2 b23 = *(const ulonglong2*)&Ws[kk * 64 + tx * 8 + 4];
            #pragma unroll
            for (int i = 0; i < 8; i++) {
                unsigned long long ad = dup2(xrow[i * 69 + kk]);
                ffma2(acc[i][0], ad, b01.x);
                ffma2(acc[i][1], ad, b01.y);
                ffma2(acc[i][2], ad, b23.x);
                ffma2(acc[i][3], ad, b23.y);
            }
        }
        __syncthreads();
    }

    #pragma unroll
    for (int i = 0; i < 8; i++) {
        int node = n0 + ty * 8 + i;
        if (node < N) {
            float2 p0 = u2f2(acc[i][0]), p1 = u2f2(acc[i][1]);
            float2 p2 = u2f2(acc[i][2]), p3 = u2f2(acc[i][3]);
            *(float4*)&g_xw[node * 64 + tx * 8]     = make_float4(p0.x, p0.y, p1.x, p1.y);
            *(float4*)&g_xw[node * 64 + tx * 8 + 4] = make_float4(p2.x, p2.y, p3.x, p3.y);
        }
    }
}

// ---- K2: edge pass 1 (weighted).  8 threads/edge, 1 LDG.128 + 1 RED.128 each ----
__global__ void __launch_bounds__(256) k_edge1(const float* __restrict__ ew, int E) {
    int t = blockIdx.x * 256 + threadIdx.x;
    int e = t >> 3, p = t & 7;
    if (e >= E) return;
    int s = g_src[e];
    int d = g_dst[e];
    float w = ew[e];
    float4 v = *(const float4*)&g_xw[s * 64 + p * 4];   // rel-projected cols 0..31
    v.x *= w; v.y *= w; v.z *= w; v.w *= w;
    red_add4(&g_sum1[d * 32 + p * 4], v);
}

// ---- K3: combine layer 1 + project layer 2 ----
__global__ void __launch_bounds__(256) k_comb1(
    const float* __restrict__ b1,
    const float* __restrict__ Wrel2,    // [32][5]
    const float* __restrict__ Wroot2,   // [32][5]
    int N)
{
    __shared__ float sW[352];  // [0..159]=Wrel2, [160..319]=Wroot2, [320..351]=b1
    int t = threadIdx.x;
    for (int i = t; i < 352; i += 256) {
        sW[i] = (i < 160) ? Wrel2[i]
              : (i < 320) ? Wroot2[i - 160]
                          : b1[i - 320];
    }
    __syncthreads();

    int node = blockIdx.x * 256 + t;
    if (node >= N) return;

    float inv = 1.0f / fmaxf(g_cnt[node], 1.0f);
    const float4* sp = (const float4*)&g_sum1[node * 32];
    const float4* rp = (const float4*)&g_xw[node * 64 + 32];

    float h[32];
    #pragma unroll
    for (int q = 0; q < 8; q++) {
        float4 s4 = sp[q];
        float4 r4 = rp[q];
        h[4 * q + 0] = fmaxf(s4.x * inv + r4.x + sW[320 + 4 * q + 0], 0.f);
        h[4 * q + 1] = fmaxf(s4.y * inv + r4.y + sW[320 + 4 * q + 1], 0.f);
        h[4 * q + 2] = fmaxf(s4.z * inv + r4.z + sW[320 + 4 * q + 2], 0.f);
        h[4 * q + 3] = fmaxf(s4.w * inv + r4.w + sW[320 + 4 * q + 3], 0.f);
    }

    float hr[5] = {0.f, 0.f, 0.f, 0.f, 0.f};
    float ho[5] = {0.f, 0.f, 0.f, 0.f, 0.f};
    #pragma unroll
    for (int j = 0; j < 32; j++) {
        float hv = h[j];
        #pragma unroll
        for (int c = 0; c < 5; c++) {
            hr[c] += hv * sW[j * 5 + c];
            ho[c] += hv * sW[160 + j * 5 + c];
        }
    }
    *(float4*)&g_hr[node * 8 + 0]    = make_float4(hr[0], hr[1], hr[2], hr[3]);
    *(float4*)&g_hr[node * 8 + 4]    = make_float4(hr[4], 0.f, 0.f, 0.f);
    *(float4*)&g_hroot[node * 8 + 0] = make_float4(ho[0], ho[1], ho[2], ho[3]);
    *(float4*)&g_hroot[node * 8 + 4] = make_float4(ho[4], 0.f, 0.f, 0.f);
}

// ---- K4: edge pass 2 (unweighted).  2 threads/edge, RED.128 (cols 5..7 zero-pad) ----
__global__ void __launch_bounds__(256) k_edge2(int E) {
    int t = blockIdx.x * 256 + threadIdx.x;
    int e = t >> 1, p = t & 1;
    if (e >= E) return;
    int s = g_src[e];
    int d = g_dst[e];
    float4 v = *(const float4*)&g_hr[s * 8 + p * 4];
    red_add4(&g_sum2[d * 8 + p * 4], v);
}

// ---- K5: combine layer 2 + log_softmax ----
__global__ void __launch_bounds__(256) k_final(
    const float* __restrict__ b2,
    float* __restrict__ out,
    int N)
{
    int node = blockIdx.x * 256 + threadIdx.x;
    if (node >= N) return;
    float inv = 1.0f / fmaxf(g_cnt[node], 1.0f);
    float v[5];
    #pragma unroll
    for (int c = 0; c < 5; c++)
        v[c] = g_sum2[node * 8 + c] * inv + g_hroot[node * 8 + c] + b2[c];

    float m = v[0];
    #pragma unroll
    for (int c = 1; c < 5; c++) m = fmaxf(m, v[c]);
    float sum = 0.f;
    #pragma unroll
    for (int c = 0; c < 5; c++) sum += expf(v[c] - m);
    float lse = m + logf(sum);
    #pragma unroll
    for (int c = 0; c < 5; c++) out[node * 5 + c] = v[c] - lse;
}

extern "C" void kernel_launch(void* const* d_in, const int* in_sizes, int n_in,
                              void* d_out, int out_size)
{
    const float* x      = (const float*)d_in[0];
    const int*   ei     = (const int*)d_in[1];     // raw words; layout detected on device
    const float* ew     = (const float*)d_in[2];
    const float* Wrel1  = (const float*)d_in[3];
    const float* Wroot1 = (const float*)d_in[4];
    const float* b1     = (const float*)d_in[5];
    const float* Wrel2  = (const float*)d_in[6];
    const float* Wroot2 = (const float*)d_in[7];
    const float* b2     = (const float*)d_in[8];
    float*       out    = (float*)d_out;

    int N = out_size / 5;          // output [N,5]
    int E = in_sizes[1] / 2;       // edge_index [2,E]

    const int GEMM_SMEM = (4096 + 256 * 69) * 4;   // 87040 B
    cudaFuncSetAttribute(k_gemm1, cudaFuncAttributeMaxDynamicSharedMemorySize, GEMM_SMEM);

    k_detect<<<1, 64>>>(ei);
    k_zero  <<<2048, 256>>>(N);
    k_unpack<<<(E + 255) / 256, 256>>>(ei, E, N);
    k_gemm1 <<<(N + 255) / 256, 256, GEMM_SMEM>>>(x, Wrel1, Wroot1, N);
    k_edge1 <<<(E * 8 + 255) / 256, 256>>>(ew, E);
    k_comb1 <<<(N + 255) / 256, 256>>>(b1, Wrel2, Wroot2, N);
    k_edge2 <<<(E * 2 + 255) / 256, 256>>>(E);
    k_final <<<(N + 255) / 256, 256>>>(b2, out, N);
}